// round 8
// baseline (speedup 1.0000x reference)
#include <cuda_runtime.h>
#include <stdint.h>

#define GRID_RES 64
#define BB 8
#define NN 4096
#define KC 55                         // 440 blocks = one 3-resident wave (<=444)
#define CH 75                         // 55*75 = 4125 >= 4096
#define TILE 16
#define TTILES 5                      // 75 -> 80 padded (mask=drop on pad)
#define RF_STRIDE 194                 // 192 + pad
#define CF_STRIDE 72                  // cf_pad(63)=67 max, 16B-aligned stride
#define PART_ELEMS (3 * 64 * 64)

__device__ float g_partial[BB * KC * PART_ELEMS];

typedef unsigned long long u64;

__device__ __forceinline__ float ex2f(float x) {
    float r;
    asm("ex2.approx.f32 %0, %1;" : "=f"(r) : "f"(x));
    return r;
}

// packed f32x2 FMA: d += a*b componentwise (sm_103a FFMA2)
#define FMA2(d, a, b) asm("fma.rn.f32x2 %0, %1, %2, %0;" : "+l"(d) : "l"(a), "l"(b))
#define PACK2(d, f)   asm("mov.b64 %0, {%1, %1};" : "=l"(d) : "f"(f))
#define UNPACK2(lo, hi, d) asm("mov.b64 {%0, %1}, %2;" : "=f"(lo), "=f"(hi) : "l"(d))

// +4-float gap after every 32 CF columns: the four LDS.128 address groups
// {cg, cg+4, cg+8, cg+12} for cg in padded {0,16,36,52} are bank-disjoint.
__device__ __forceinline__ int cf_pad(int jx) { return jx + ((jx >> 5) << 2); }

__global__ __launch_bounds__(256, 3)
void rbf_partial_kernel(const float* __restrict__ xc,
                        const float* __restrict__ yc,
                        const float* __restrict__ tc,
                        const int* __restrict__ mask) {
    const int b = blockIdx.y;
    const int kc = blockIdx.x;
    const int tid = threadIdx.x;

    const float CEXP = -72.13475204444817f;  // -50 * log2(e)
    const float STEP = 2.0f / 63.0f;

    __shared__ float sRF[2][TILE][RF_STRIDE]; // [ch*64+iy]: wy*mf, wy*y*mf, wy*t*mf
    __shared__ float sCF[2][TILE][CF_STRIDE]; // wx, pad-interleaved
    __shared__ float sP[2][TILE][8];          // px, py, mf, y*mf, t*mf

    // stage-B: thread owns row iy x 16 cols (cg..cg+15) x 3 ch
    // acc[ch][c] packs (col cg+2c, col cg+2c+1)
    u64 acc[3][8];
#pragma unroll
    for (int ch = 0; ch < 3; ch++)
#pragma unroll
        for (int c = 0; c < 8; c++) acc[ch][c] = 0ULL;

    const int iy = tid >> 2;            // 0..63
    const int cg = (tid & 3) << 4;      // 0,16,32,48
    const int cfp = cf_pad(cg);

    // stage-A roles: tid<192 -> RF thread (ch = tid>>6, iyA = tid&63);
    //                tid>=192 -> CF thread (jx = tid-192)
    const bool isRF = (tid < 192);
    const int chA = tid >> 6;                    // 0..2 for RF
    const int iyA = tid & 63;
    const int jx = tid - 192;
    const float gvy = -1.0f + STEP * (float)iyA; // gy for RF
    const float gvx = -1.0f + STEP * (float)jx;  // gx for CF
    const int jxp = (jx >= 0) ? cf_pad(jx) : 0;
    const int rfo = chA * 64 + iyA;              // RF write offset
    const int fsel = 2 + chA;                    // sP feature column

    const int p0 = kc * CH;
    const int p1 = min(p0 + CH, NN);

    // point staging registers (thread tid<16 stages point tid of tile tt)
    float Px = 0.f, Py = 0.f, Mf = 0.f, Ym = 0.f, Tm = 0.f;

#define LOADP(tt)                                                         \
    do {                                                                  \
        if (tid < TILE && (tt) < TTILES) {                                \
            const int n = p0 + (tt) * TILE + tid;                         \
            if (n < p1) {                                                 \
                Px = xc[(b * NN + n) * 2 + 0];                            \
                Py = xc[(b * NN + n) * 2 + 1];                            \
                Mf = (mask[b * NN + n] != 0) ? 0.0f : 1.0f;               \
                Ym = yc[b * NN + n] * Mf;                                 \
                Tm = tc[b * NN + n] * Mf;                                 \
            } else { Px = Py = Mf = Ym = Tm = 0.0f; }                     \
        }                                                                 \
    } while (0)

#define STSP(tt)                                                          \
    do {                                                                  \
        if (tid < TILE && (tt) < TTILES) {                                \
            const int bb_ = (tt) & 1;                                     \
            sP[bb_][tid][0] = Px; sP[bb_][tid][1] = Py;                   \
            sP[bb_][tid][2] = Mf; sP[bb_][tid][3] = Ym;                   \
            sP[bb_][tid][4] = Tm;                                         \
        }                                                                 \
    } while (0)

#define STAGE_A(tt)                                                       \
    do {                                                                  \
        const int bb_ = (tt) & 1;                                         \
        if (isRF) {                                                       \
            _Pragma("unroll")                                             \
            for (int p = 0; p < TILE; p++) {                              \
                const float dy = sP[bb_][p][1] - gvy;                     \
                const float wy = ex2f(CEXP * dy * dy);                    \
                sRF[bb_][p][rfo] = wy * sP[bb_][p][fsel];                 \
            }                                                             \
        } else {                                                          \
            _Pragma("unroll")                                             \
            for (int p = 0; p < TILE; p++) {                              \
                const float dx = sP[bb_][p][0] - gvx;                     \
                sCF[bb_][p][jxp] = ex2f(CEXP * dx * dx);                  \
            }                                                             \
        }                                                                 \
    } while (0)

#define STAGE_B(tt)                                                       \
    do {                                                                  \
        const int bb_ = (tt) & 1;                                         \
        _Pragma("unroll 4")                                               \
        for (int p = 0; p < TILE; p++) {                                  \
            const float4 cA = *(const float4*)&sCF[bb_][p][cfp + 0];      \
            const float4 cB = *(const float4*)&sCF[bb_][p][cfp + 4];      \
            const float4 cC = *(const float4*)&sCF[bb_][p][cfp + 8];      \
            const float4 cD = *(const float4*)&sCF[bb_][p][cfp + 12];     \
            const u64* cp0 = (const u64*)&cA;                             \
            const u64* cp1 = (const u64*)&cB;                             \
            const u64* cp2 = (const u64*)&cC;                             \
            const u64* cp3 = (const u64*)&cD;                             \
            u64 r[3];                                                     \
            PACK2(r[0], sRF[bb_][p][iy]);                                 \
            PACK2(r[1], sRF[bb_][p][64 + iy]);                            \
            PACK2(r[2], sRF[bb_][p][128 + iy]);                           \
            _Pragma("unroll")                                             \
            for (int ch = 0; ch < 3; ch++) {                              \
                FMA2(acc[ch][0], r[ch], cp0[0]);                          \
                FMA2(acc[ch][1], r[ch], cp0[1]);                          \
                FMA2(acc[ch][2], r[ch], cp1[0]);                          \
                FMA2(acc[ch][3], r[ch], cp1[1]);                          \
                FMA2(acc[ch][4], r[ch], cp2[0]);                          \
                FMA2(acc[ch][5], r[ch], cp2[1]);                          \
                FMA2(acc[ch][6], r[ch], cp3[0]);                          \
                FMA2(acc[ch][7], r[ch], cp3[1]);                          \
            }                                                             \
        }                                                                 \
    } while (0)

    // prologue
    LOADP(0); STSP(0);
    LOADP(1); STSP(1);
    LOADP(2);
    __syncthreads();
    STAGE_A(0);
    __syncthreads();

    // pipelined main loop: one barrier per tile
#pragma unroll 1
    for (int t = 0; t < TTILES; t++) {
        STSP(t + 2);
        LOADP(t + 3);
        if (t + 1 < TTILES) STAGE_A(t + 1);
        STAGE_B(t);
        __syncthreads();
    }

    // epilogue: [ch][iy][jx] = ch*4096 + iy*64 + jx; 16 contiguous cols
    float* dst = &g_partial[(b * KC + kc) * PART_ELEMS];
#pragma unroll
    for (int ch = 0; ch < 3; ch++) {
        float v[16];
#pragma unroll
        for (int c = 0; c < 8; c++) UNPACK2(v[2 * c], v[2 * c + 1], acc[ch][c]);
        float* d0 = &dst[ch * 4096 + iy * 64 + cg];
        *(float4*)&d0[0]  = make_float4(v[0], v[1], v[2], v[3]);
        *(float4*)&d0[4]  = make_float4(v[4], v[5], v[6], v[7]);
        *(float4*)&d0[8]  = make_float4(v[8], v[9], v[10], v[11]);
        *(float4*)&d0[12] = make_float4(v[12], v[13], v[14], v[15]);
    }
}

// K2: density reduce (channel 0). 32768 threads.
__global__ __launch_bounds__(256)
void rbf_density_kernel(float* __restrict__ out) {
    const int idx = blockIdx.x * blockDim.x + threadIdx.x;
    const int b = idx >> 12;
    const int g = idx & 4095;
    const float* base = &g_partial[b * KC * PART_ELEMS + g];
    float s = 0.0f;
#pragma unroll
    for (int kcc = 0; kcc < KC; kcc++) s += base[kcc * PART_ELEMS];
    out[b * PART_ELEMS + g] = s;
}

// K3: weighted channels + divide by (density + eps). 65536 threads.
__global__ __launch_bounds__(256)
void rbf_weighted_kernel(float* __restrict__ out) {
    const int idx = blockIdx.x * blockDim.x + threadIdx.x;
    const int b = idx >> 13;
    const int r = idx & 8191;
    const int ch = 1 + (r >> 12);
    const int g = r & 4095;
    const float* base = &g_partial[b * KC * PART_ELEMS + ch * 4096 + g];
    float s = 0.0f;
#pragma unroll
    for (int kcc = 0; kcc < KC; kcc++) s += base[kcc * PART_ELEMS];
    const float d = out[b * PART_ELEMS + g];
    out[b * PART_ELEMS + ch * 4096 + g] = s / (d + 1e-5f);
}

extern "C" void kernel_launch(void* const* d_in, const int* in_sizes, int n_in,
                              void* d_out, int out_size) {
    const float* xc = (const float*)d_in[0];
    const float* yc = (const float*)d_in[1];
    const float* tc = (const float*)d_in[2];
    const int* mask = (const int*)d_in[3];

    dim3 grid(KC, BB);
    rbf_partial_kernel<<<grid, 256>>>(xc, yc, tc, mask);

    rbf_density_kernel<<<128, 256>>>((float*)d_out);
    rbf_weighted_kernel<<<256, 256>>>((float*)d_out);
}

// round 9
// speedup vs baseline: 1.1080x; 1.1080x over previous
#include <cuda_runtime.h>
#include <stdint.h>

#define GRID_RES 64
#define BB 8
#define NN 4096
#define KC 55                         // 440 blocks = one 3-resident wave
#define CH 75                         // 55*75 = 4125 >= 4096
#define TILE 16
#define TTILES 5                      // 80 padded slots (mask=drop on pad)
#define RF_STRIDE 194
#define CF_STRIDE 72
#define SP_STRIDE 9                   // odd-ish stride: kills sP bank conflicts
#define PART_ELEMS (3 * 64 * 64)

__device__ float g_partial[BB * KC * PART_ELEMS];

typedef unsigned long long u64;

__device__ __forceinline__ float ex2f(float x) {
    float r;
    asm("ex2.approx.f32 %0, %1;" : "=f"(r) : "f"(x));
    return r;
}

// packed f32x2 FMA: d += a*b componentwise (sm_103a FFMA2)
#define FMA2(d, a, b) asm("fma.rn.f32x2 %0, %1, %2, %0;" : "+l"(d) : "l"(a), "l"(b))
#define PACK2(d, f)   asm("mov.b64 %0, {%1, %1};" : "=l"(d) : "f"(f))
#define UNPACK2(lo, hi, d) asm("mov.b64 {%0, %1}, %2;" : "=f"(lo), "=f"(hi) : "l"(d))

// +4-float gap after every 32 CF cols: LDS.128 groups land on disjoint banks
__device__ __forceinline__ int cf_pad(int jx) { return jx + ((jx >> 5) << 2); }

__global__ __launch_bounds__(256, 3)
void rbf_partial_kernel(const float* __restrict__ xc,
                        const float* __restrict__ yc,
                        const float* __restrict__ tc,
                        const int* __restrict__ mask) {
    const int b = blockIdx.y;
    const int kc = blockIdx.x;
    const int tid = threadIdx.x;

    const float CEXP = -72.13475204444817f;  // -50 * log2(e)
    const float STEP = 2.0f / 63.0f;

    __shared__ float sRF[2][TILE][RF_STRIDE]; // [ch*64+row]: wy*mf, wy*ym, wy*tm
    __shared__ float sCF[2][TILE][CF_STRIDE]; // wx, pad-interleaved
    __shared__ float sP[2][TILE][SP_STRIDE];  // px, py, mf, ym, tm

    // stage-B: thread = (row-pair rp, col-oct c8); cols packed in f32x2.
    // acc[ch][r][cp] = {out[row0+r][8c8+2cp], out[row0+r][8c8+2cp+1]}
    u64 acc[3][2][4];
#pragma unroll
    for (int ch = 0; ch < 3; ch++)
#pragma unroll
        for (int r = 0; r < 2; r++)
#pragma unroll
            for (int c = 0; c < 4; c++) acc[ch][r][c] = 0ULL;

    const int rp = tid >> 3;            // 0..31
    const int row0 = rp << 1;
    const int c8 = tid & 7;
    const int cfp = cf_pad(c8 << 3);

    // stage-A: every thread does BOTH roles (no divergence).
    // row index == col index == rr; same grid coordinate constant.
    const int rr = tid >> 2;            // 0..63
    const int ptq = tid & 3;            // point-quarter
    const float gv = -1.0f + STEP * (float)rr;
    const int cfw = cf_pad(rr);

    const int p0 = kc * CH;
    const int p1 = min(p0 + CH, NN);

    float Px = 0.f, Py = 0.f, Mf = 0.f, Ym = 0.f, Tm = 0.f;

#define LOADP(tt)                                                         \
    do {                                                                  \
        if (tid < TILE && (tt) < TTILES) {                                \
            const int n = p0 + (tt) * TILE + tid;                         \
            if (n < p1) {                                                 \
                Px = xc[(b * NN + n) * 2 + 0];                            \
                Py = xc[(b * NN + n) * 2 + 1];                            \
                Mf = (mask[b * NN + n] != 0) ? 0.0f : 1.0f;               \
                Ym = yc[b * NN + n] * Mf;                                 \
                Tm = tc[b * NN + n] * Mf;                                 \
            } else { Px = Py = Mf = Ym = Tm = 0.0f; }                     \
        }                                                                 \
    } while (0)

#define STSP(tt)                                                          \
    do {                                                                  \
        if (tid < TILE && (tt) < TTILES) {                                \
            const int bb_ = (tt) & 1;                                     \
            sP[bb_][tid][0] = Px; sP[bb_][tid][1] = Py;                   \
            sP[bb_][tid][2] = Mf; sP[bb_][tid][3] = Ym;                   \
            sP[bb_][tid][4] = Tm;                                         \
        }                                                                 \
    } while (0)

// RF role uses points pa = 4*ptq + q (conflict-free STS at stride 194);
// CF role uses points pb = ptq + 4*q (conflict-free STS at stride 72).
#define STAGE_A(tt)                                                       \
    do {                                                                  \
        const int bb_ = (tt) & 1;                                         \
        _Pragma("unroll")                                                 \
        for (int q = 0; q < 4; q++) {                                     \
            const int pa = 4 * ptq + q;                                   \
            const float dy = sP[bb_][pa][1] - gv;                         \
            const float w = ex2f(CEXP * dy * dy);                         \
            sRF[bb_][pa][rr] = w * sP[bb_][pa][2];                        \
            sRF[bb_][pa][64 + rr] = w * sP[bb_][pa][3];                   \
            sRF[bb_][pa][128 + rr] = w * sP[bb_][pa][4];                  \
            const int pb = ptq + 4 * q;                                   \
            const float dx = sP[bb_][pb][0] - gv;                         \
            sCF[bb_][pb][cfw] = ex2f(CEXP * dx * dx);                     \
        }                                                                 \
    } while (0)

#define STAGE_B(tt)                                                       \
    do {                                                                  \
        const int bb_ = (tt) & 1;                                         \
        _Pragma("unroll 4")                                               \
        for (int p = 0; p < TILE; p++) {                                  \
            const float4 cA = *(const float4*)&sCF[bb_][p][cfp + 0];      \
            const float4 cB = *(const float4*)&sCF[bb_][p][cfp + 4];      \
            const u64* cp = (const u64*)&cA;   /* packed col-pairs */     \
            const u64* cq = (const u64*)&cB;                              \
            u64 rep[3][2];                                                \
            _Pragma("unroll")                                             \
            for (int ch = 0; ch < 3; ch++) {                              \
                const u64 rr2 = *(const u64*)&sRF[bb_][p][ch * 64 + row0];\
                float rl, rh;                                             \
                UNPACK2(rl, rh, rr2);                                     \
                PACK2(rep[ch][0], rl);                                    \
                PACK2(rep[ch][1], rh);                                    \
            }                                                             \
            _Pragma("unroll")                                             \
            for (int ch = 0; ch < 3; ch++) {                              \
                _Pragma("unroll")                                         \
                for (int r = 0; r < 2; r++) {                             \
                    FMA2(acc[ch][r][0], rep[ch][r], cp[0]);               \
                    FMA2(acc[ch][r][1], rep[ch][r], cp[1]);               \
                    FMA2(acc[ch][r][2], rep[ch][r], cq[0]);               \
                    FMA2(acc[ch][r][3], rep[ch][r], cq[1]);               \
                }                                                         \
            }                                                             \
        }                                                                 \
    } while (0)

    // prologue
    LOADP(0); STSP(0);
    LOADP(1); STSP(1);
    LOADP(2);
    __syncthreads();
    STAGE_A(0);
    __syncthreads();

    // pipelined main loop: one barrier per tile
#pragma unroll 1
    for (int t = 0; t < TTILES; t++) {
        STSP(t + 2);
        LOADP(t + 3);
        if (t + 1 < TTILES) STAGE_A(t + 1);
        STAGE_B(t);
        __syncthreads();
    }

    // epilogue: [ch][row][col] = ch*4096 + row*64 + col
    float* dst = &g_partial[(b * KC + kc) * PART_ELEMS];
#pragma unroll
    for (int ch = 0; ch < 3; ch++) {
#pragma unroll
        for (int r = 0; r < 2; r++) {
            float v[8];
#pragma unroll
            for (int c = 0; c < 4; c++) UNPACK2(v[2 * c], v[2 * c + 1], acc[ch][r][c]);
            float* d0 = &dst[ch * 4096 + (row0 + r) * 64 + (c8 << 3)];
            *(float4*)&d0[0] = make_float4(v[0], v[1], v[2], v[3]);
            *(float4*)&d0[4] = make_float4(v[4], v[5], v[6], v[7]);
        }
    }
}

// K2: density reduce (channel 0). 32768 threads.
__global__ __launch_bounds__(256)
void rbf_density_kernel(float* __restrict__ out) {
    const int idx = blockIdx.x * blockDim.x + threadIdx.x;
    const int b = idx >> 12;
    const int g = idx & 4095;
    const float* base = &g_partial[b * KC * PART_ELEMS + g];
    float s = 0.0f;
#pragma unroll
    for (int kcc = 0; kcc < KC; kcc++) s += base[kcc * PART_ELEMS];
    out[b * PART_ELEMS + g] = s;
}

// K3: weighted channels + divide by (density + eps). 65536 threads.
__global__ __launch_bounds__(256)
void rbf_weighted_kernel(float* __restrict__ out) {
    const int idx = blockIdx.x * blockDim.x + threadIdx.x;
    const int b = idx >> 13;
    const int r = idx & 8191;
    const int ch = 1 + (r >> 12);
    const int g = r & 4095;
    const float* base = &g_partial[b * KC * PART_ELEMS + ch * 4096 + g];
    float s = 0.0f;
#pragma unroll
    for (int kcc = 0; kcc < KC; kcc++) s += base[kcc * PART_ELEMS];
    const float d = out[b * PART_ELEMS + g];
    out[b * PART_ELEMS + ch * 4096 + g] = s / (d + 1e-5f);
}

extern "C" void kernel_launch(void* const* d_in, const int* in_sizes, int n_in,
                              void* d_out, int out_size) {
    const float* xc = (const float*)d_in[0];
    const float* yc = (const float*)d_in[1];
    const float* tc = (const float*)d_in[2];
    const int* mask = (const int*)d_in[3];

    dim3 grid(KC, BB);
    rbf_partial_kernel<<<grid, 256>>>(xc, yc, tc, mask);

    rbf_density_kernel<<<128, 256>>>((float*)d_out);
    rbf_weighted_kernel<<<256, 256>>>((float*)d_out);
}

// round 10
// speedup vs baseline: 1.1757x; 1.0611x over previous
#include <cuda_runtime.h>
#include <stdint.h>

#define GRID_RES 64
#define BB 8
#define NN 4096
#define KC 55                         // 440 blocks ~ 3-resident wave
#define CH 75                         // 55*75 = 4125 >= 4096
#define TILE 16
#define TTILES 5                      // 80 slots, pad -> zero contribution
#define RF_STRIDE 194                 // even (8B-aligned row-pairs), 194%32=2
#define CFD_STRIDE 144                // duplicated CF row; 144%32=16 -> 2-wf STS.64
#define SP_STRIDE 9
#define PART_ELEMS (3 * 64 * 64)

// partials stored TRANSPOSED: [ch][col][row]  (offset ch*4096 + col*64 + row)
__device__ float g_partial[BB * KC * PART_ELEMS];

typedef unsigned long long u64;

__device__ __forceinline__ float ex2f(float x) {
    float r;
    asm("ex2.approx.f32 %0, %1;" : "=f"(r) : "f"(x));
    return r;
}

// packed f32x2 FMA: d += a*b componentwise (sm_103a FFMA2)
#define FMA2(d, a, b) asm("fma.rn.f32x2 %0, %1, %2, %0;" : "+l"(d) : "l"(a), "l"(b))
#define PACK2(d, f)   asm("mov.b64 %0, {%1, %1};" : "=l"(d) : "f"(f))

__global__ __launch_bounds__(256, 3)
void rbf_partial_kernel(const float* __restrict__ xc,
                        const float* __restrict__ yc,
                        const float* __restrict__ tc,
                        const int* __restrict__ mask) {
    const int b = blockIdx.y;
    const int kc = blockIdx.x;
    const int tid = threadIdx.x;

    const float CEXP = -72.13475204444817f;  // -50 * log2(e)
    const float STEP = 2.0f / 63.0f;

    __shared__ float sRF[2][TILE][RF_STRIDE];   // [ch*64+row]: wy*mf, wy*ym, wy*tm
    __shared__ float sCFd[2][TILE][CFD_STRIDE]; // duplicated wx pairs: [2*col]={wx,wx}
    __shared__ float sP[2][TILE][SP_STRIDE];    // px, py, mf, ym, tm

    // stage-B: warp w = col-octave (tid>>5), lane l = row-pair (tid&31)
    // acc[ch][c] = {out[ch][2l][8w+c], out[ch][2l+1][8w+c]}  (row-pair packed)
    u64 acc[3][8];
#pragma unroll
    for (int ch = 0; ch < 3; ch++)
#pragma unroll
        for (int c = 0; c < 8; c++) acc[ch][c] = 0ULL;

    const int w = tid >> 5;             // warp id = col octave
    const int lane = tid & 31;
    const int row0 = lane << 1;
    const int cfo = w << 4;             // float offset of duplicated col group

    // stage-A: every thread does both roles; row idx == col idx == rr
    const int rr = tid >> 2;            // 0..63
    const int ptq = tid & 3;
    const float gv = -1.0f + STEP * (float)rr;

    const int p0 = kc * CH;
    const int p1 = min(p0 + CH, NN);

    float Px = 0.f, Py = 0.f, Mf = 0.f, Ym = 0.f, Tm = 0.f;

#define LOADP(tt)                                                         \
    do {                                                                  \
        if (tid < TILE && (tt) < TTILES) {                                \
            const int n = p0 + (tt) * TILE + tid;                         \
            if (n < p1) {                                                 \
                Px = xc[(b * NN + n) * 2 + 0];                            \
                Py = xc[(b * NN + n) * 2 + 1];                            \
                Mf = (mask[b * NN + n] != 0) ? 0.0f : 1.0f;               \
                Ym = yc[b * NN + n] * Mf;                                 \
                Tm = tc[b * NN + n] * Mf;                                 \
            } else { Px = Py = Mf = Ym = Tm = 0.0f; }                     \
        }                                                                 \
    } while (0)

#define STSP(tt)                                                          \
    do {                                                                  \
        if (tid < TILE && (tt) < TTILES) {                                \
            const int bb_ = (tt) & 1;                                     \
            sP[bb_][tid][0] = Px; sP[bb_][tid][1] = Py;                   \
            sP[bb_][tid][2] = Mf; sP[bb_][tid][3] = Ym;                   \
            sP[bb_][tid][4] = Tm;                                         \
        }                                                                 \
    } while (0)

// RF role: points pa = 4*ptq+q  -> STS.32 banks (rr + 8*ptq)%32: tiles all 32, 1 wf
// CF role: points pb = ptq+4*q  -> STS.64 at stride 144 (16 mod 32): exactly 2 wf
#define STAGE_A(tt)                                                       \
    do {                                                                  \
        const int bb_ = (tt) & 1;                                         \
        _Pragma("unroll")                                                 \
        for (int q = 0; q < 4; q++) {                                     \
            const int pa = 4 * ptq + q;                                   \
            const float dy = sP[bb_][pa][1] - gv;                         \
            const float wv = ex2f(CEXP * dy * dy);                        \
            sRF[bb_][pa][rr] = wv * sP[bb_][pa][2];                       \
            sRF[bb_][pa][64 + rr] = wv * sP[bb_][pa][3];                  \
            sRF[bb_][pa][128 + rr] = wv * sP[bb_][pa][4];                 \
            const int pb = ptq + 4 * q;                                   \
            const float dx = sP[bb_][pb][0] - gv;                         \
            const float wx = ex2f(CEXP * dx * dx);                        \
            u64 dd;                                                       \
            PACK2(dd, wx);                                                \
            *(u64*)&sCFd[bb_][pb][2 * rr] = dd;                           \
        }                                                                 \
    } while (0)

#define STAGE_B(tt)                                                       \
    do {                                                                  \
        const int bb_ = (tt) & 1;                                         \
        _Pragma("unroll 8")                                               \
        for (int p = 0; p < TILE; p++) {                                  \
            const float4* cf = (const float4*)&sCFd[bb_][p][cfo];         \
            const float4 f0 = cf[0];   /* broadcast: whole warp same addr */ \
            const float4 f1 = cf[1];                                      \
            const float4 f2 = cf[2];                                      \
            const float4 f3 = cf[3];                                      \
            const u64* c01 = (const u64*)&f0;                             \
            const u64* c23 = (const u64*)&f1;                             \
            const u64* c45 = (const u64*)&f2;                             \
            const u64* c67 = (const u64*)&f3;                             \
            const u64 r0 = *(const u64*)&sRF[bb_][p][row0];               \
            const u64 r1 = *(const u64*)&sRF[bb_][p][64 + row0];          \
            const u64 r2 = *(const u64*)&sRF[bb_][p][128 + row0];         \
            FMA2(acc[0][0], r0, c01[0]); FMA2(acc[0][1], r0, c01[1]);     \
            FMA2(acc[0][2], r0, c23[0]); FMA2(acc[0][3], r0, c23[1]);     \
            FMA2(acc[0][4], r0, c45[0]); FMA2(acc[0][5], r0, c45[1]);     \
            FMA2(acc[0][6], r0, c67[0]); FMA2(acc[0][7], r0, c67[1]);     \
            FMA2(acc[1][0], r1, c01[0]); FMA2(acc[1][1], r1, c01[1]);     \
            FMA2(acc[1][2], r1, c23[0]); FMA2(acc[1][3], r1, c23[1]);     \
            FMA2(acc[1][4], r1, c45[0]); FMA2(acc[1][5], r1, c45[1]);     \
            FMA2(acc[1][6], r1, c67[0]); FMA2(acc[1][7], r1, c67[1]);     \
            FMA2(acc[2][0], r2, c01[0]); FMA2(acc[2][1], r2, c01[1]);     \
            FMA2(acc[2][2], r2, c23[0]); FMA2(acc[2][3], r2, c23[1]);     \
            FMA2(acc[2][4], r2, c45[0]); FMA2(acc[2][5], r2, c45[1]);     \
            FMA2(acc[2][6], r2, c67[0]); FMA2(acc[2][7], r2, c67[1]);     \
        }                                                                 \
    } while (0)

    // prologue
    LOADP(0); STSP(0);
    LOADP(1); STSP(1);
    LOADP(2);
    __syncthreads();
    STAGE_A(0);
    __syncthreads();

#pragma unroll 1
    for (int t = 0; t < TTILES; t++) {
        STSP(t + 2);
        LOADP(t + 3);
        if (t + 1 < TTILES) STAGE_A(t + 1);
        STAGE_B(t);
        __syncthreads();
    }

    // epilogue into TRANSPOSED partials [ch][col][row]:
    // acc[ch][c] holds rows (row0,row0+1) at col 8w+c -> contiguous STG.64,
    // warp lanes cover rows 0..63 -> 256B coalesced per (ch,c).
    float* dst = &g_partial[(b * KC + kc) * PART_ELEMS];
#pragma unroll
    for (int ch = 0; ch < 3; ch++) {
#pragma unroll
        for (int c = 0; c < 8; c++) {
            *(u64*)&dst[ch * 4096 + (8 * w + c) * 64 + row0] = acc[ch][c];
        }
    }
}

// Fused finalize: 98304 threads, one per (b, ch, transposed-cell gp).
// ch>0 threads recompute density with identical summation order (bitwise-equal
// divisor). Reads coalesced over gp; writes de-transposed (scattered, cheap).
__global__ __launch_bounds__(256)
void rbf_finalize_kernel(float* __restrict__ out) {
    const int idx = blockIdx.x * blockDim.x + threadIdx.x;  // 384*256 = 98304
    const int b = idx / 12288;
    const int r = idx - b * 12288;
    const int ch = r >> 12;
    const int gp = r & 4095;           // gp = col*64 + row
    const int row = gp & 63;
    const int col = gp >> 6;

    const float* base = &g_partial[b * KC * PART_ELEMS];
    float s = 0.0f;
#pragma unroll
    for (int kcc = 0; kcc < KC; kcc++) s += base[kcc * PART_ELEMS + ch * 4096 + gp];

    float v;
    if (ch == 0) {
        v = s;
    } else {
        float d = 0.0f;
#pragma unroll
        for (int kcc = 0; kcc < KC; kcc++) d += base[kcc * PART_ELEMS + gp];
        v = s / (d + 1e-5f);
    }
    out[b * 12288 + ch * 4096 + row * 64 + col] = v;
}

extern "C" void kernel_launch(void* const* d_in, const int* in_sizes, int n_in,
                              void* d_out, int out_size) {
    const float* xc = (const float*)d_in[0];
    const float* yc = (const float*)d_in[1];
    const float* tc = (const float*)d_in[2];
    const int* mask = (const int*)d_in[3];

    dim3 grid(KC, BB);
    rbf_partial_kernel<<<grid, 256>>>(xc, yc, tc, mask);

    rbf_finalize_kernel<<<384, 256>>>((float*)d_out);
}